// round 12
// baseline (speedup 1.0000x reference)
#include <cuda_runtime.h>
#include <cuda_fp16.h>

#define BATCH   256
#define IN_DIM  65536
#define OUT_DIM 65536

#define NB_T 2048   // transpose tiles: (IN/128) x (B/64)
#define NB_C 256
#define NB_I 512

// ---------------- device scratch ----------------------------------------
__device__ float4 g_coef[OUT_DIM];                             // 1 MB
__device__ __align__(16) __half g_xth[(size_t)IN_DIM * BATCH]; // 32 MB
__device__ int    g_idx[2 * OUT_DIM];                          // 512 KB

// ---------------- fused prep: transpose + coef + idx (R6, proven) -------
__global__ __launch_bounds__(256) void prep_kernel(const float* __restrict__ x,
                                                   const float* __restrict__ wts,
                                                   const void*  __restrict__ idxraw) {
    __shared__ float t[4][64][33];
    int bx  = blockIdx.x;
    int tid = threadIdx.x;

    if (bx < NB_T) {
        int it = bx & 511, bt = bx >> 9;
        int i0 = it * 128, b0 = bt * 64;
        int tx = tid & 7, ty = tid >> 3;

        const float4* r0 = (const float4*)(x + (size_t)(b0 + ty)      * IN_DIM + i0);
        const float4* r1 = (const float4*)(x + (size_t)(b0 + 32 + ty) * IN_DIM + i0);
        float4 v0[4], v1[4];
        #pragma unroll
        for (int h = 0; h < 4; h++) {
            v0[h] = __ldcs(r0 + tx + 8 * h);
            v1[h] = __ldcs(r1 + tx + 8 * h);
        }
        #pragma unroll
        for (int h = 0; h < 4; h++) {
            t[h][ty   ][tx*4+0]=v0[h].x; t[h][ty   ][tx*4+1]=v0[h].y;
            t[h][ty   ][tx*4+2]=v0[h].z; t[h][ty   ][tx*4+3]=v0[h].w;
            t[h][ty+32][tx*4+0]=v1[h].x; t[h][ty+32][tx*4+1]=v1[h].y;
            t[h][ty+32][tx*4+2]=v1[h].z; t[h][ty+32][tx*4+3]=v1[h].w;
        }
        __syncthreads();
        #pragma unroll
        for (int h = 0; h < 4; h++) {
            union { uint4 u; __half2 hh[4]; } pk;
            #pragma unroll
            for (int k = 0; k < 4; k++)
                pk.hh[k] = __floats2half2_rn(t[h][8*tx + 2*k][ty], t[h][8*tx + 2*k + 1][ty]);
            *(uint4*)(g_xth + (size_t)(i0 + 32*h + ty) * BATCH + b0 + 8*tx) = pk.u;
        }
    } else if (bx < NB_T + NB_C) {
        int o = (bx - NB_T) * 256 + tid;
        float p[16];
        const float4* w4 = (const float4*)(wts + (size_t)o * 16);
        float4 q0 = w4[0], q1 = w4[1], q2 = w4[2], q3 = w4[3];
        p[0]=q0.x; p[1]=q0.y; p[2]=q0.z; p[3]=q0.w;
        p[4]=q1.x; p[5]=q1.y; p[6]=q1.z; p[7]=q1.w;
        p[8]=q2.x; p[9]=q2.y; p[10]=q2.z; p[11]=q2.w;
        p[12]=q3.x; p[13]=q3.y; p[14]=q3.z; p[15]=q3.w;
        float m = p[0];
        #pragma unroll
        for (int i = 1; i < 16; i++) m = fmaxf(m, p[i]);
        float s = 0.f;
        #pragma unroll
        for (int i = 0; i < 16; i++) { p[i] = __expf(p[i] - m); s += p[i]; }
        float inv = 1.0f / s;
        #pragma unroll
        for (int i = 0; i < 16; i++) p[i] *= inv;
        float4 c;
        c.x = p[8]+p[9]+p[10]+p[11]+p[12]+p[13]+p[14]+p[15];
        c.y = p[2]+p[3]+p[6]+p[7]-p[8]-p[9]-p[12]-p[13];
        c.z = p[4]+p[5]+p[6]+p[7]-p[8]-p[9]-p[10]-p[11];
        c.w = p[1]-p[2]-p[4]-2.f*p[6]-p[7]+p[8]+2.f*p[9]+p[11]+p[13]-p[14];
        g_coef[o] = c;
    } else {
        __shared__ int s64;
        if (tid == 0) {
            const long long* p = (const long long*)idxraw;
            int is64 = 1;
            #pragma unroll 1
            for (int j = 0; j < 64; j++) {
                long long v = p[j];
                if (v < 0 || v >= IN_DIM) { is64 = 0; break; }
            }
            s64 = is64;
        }
        __syncthreads();
        int i = (bx - NB_T - NB_C) * 256 + tid;
        g_idx[i] = s64 ? (int)((const long long*)idxraw)[i]
                       : ((const int*)idxraw)[i];
    }
}

// ---------------- main: staging-free, sector-perfect stores -------------
// Block = 16 neurons x 256 batches (4096 blocks, 256 thr).
// Warp w: neuron group g=(w>>2)*8 (8 neurons), batch chunk (w&3)*64.
// Lane l owns batches {2l, 2l+1}: 16 half2 gathers (each warp-inst reads
// 128B contiguous from one xt row), then per batch 8 outputs written as
// 2 consecutive STG.128 = one full 32B sector per lane. No smem, no bar.
__global__ __launch_bounds__(256, 4) void logic_main_kernel(float* __restrict__ out) {
    int tid = threadIdx.x;
    int w = tid >> 5, l = tid & 31;
    int o0 = blockIdx.x * 16 + (w >> 2) * 8;   // first of this warp's 8 neurons
    int bo = (w & 3) * 64 + 2 * l;             // first of this lane's 2 batches

    // hoisted coefficients for the 8 neurons (uniform across warp)
    float4 cf[8];
    #pragma unroll
    for (int r = 0; r < 8; r++) cf[r] = __ldg(&g_coef[o0 + r]);

    // 16 row gathers, 128B/warp-inst, MLP=16
    __half2 A[8], B[8];
    #pragma unroll
    for (int r = 0; r < 8; r++) {
        unsigned ra = (unsigned)__ldg(&g_idx[o0 + r]);
        unsigned rb = (unsigned)__ldg(&g_idx[OUT_DIM + o0 + r]);
        A[r] = *(const __half2*)(g_xth + (size_t)ra * BATCH + bo);
        B[r] = *(const __half2*)(g_xth + (size_t)rb * BATCH + bo);
    }

    #pragma unroll
    for (int k = 0; k < 2; k++) {
        float v[8];
        #pragma unroll
        for (int r = 0; r < 8; r++) {
            float a = k ? __high2float(A[r]) : __low2float(A[r]);
            float b = k ? __high2float(B[r]) : __low2float(B[r]);
            v[r] = fmaf(fmaf(cf[r].w, b, cf[r].y), a, fmaf(cf[r].z, b, cf[r].x));
        }
        float4* orow = (float4*)(out + (size_t)(bo + k) * OUT_DIM + o0);
        __stcs(orow,     make_float4(v[0], v[1], v[2], v[3]));
        __stcs(orow + 1, make_float4(v[4], v[5], v[6], v[7]));
    }
}

// ---------------- launch ------------------------------------------------
extern "C" void kernel_launch(void* const* d_in, const int* in_sizes, int n_in,
                              void* d_out, int out_size) {
    const float* x   = (const float*)d_in[0];
    const float* wts = (const float*)d_in[1];
    const void*  idx = d_in[2];
    float* out = (float*)d_out;

    prep_kernel<<<NB_T + NB_C + NB_I, 256>>>(x, wts, idx);
    logic_main_kernel<<<OUT_DIM / 16, 256>>>(out);
}

// round 13
// speedup vs baseline: 1.2493x; 1.2493x over previous
#include <cuda_runtime.h>
#include <cuda_fp16.h>

#define BATCH   256
#define IN_DIM  65536
#define OUT_DIM 65536

#define NB_T 2048   // transpose tiles: (IN/128) x (B/64)
#define NB_C 256
#define NB_I 512

// ---------------- device scratch ----------------------------------------
__device__ float4 g_coef[OUT_DIM];                             // 1 MB
__device__ __align__(16) __half g_xth[(size_t)IN_DIM * BATCH]; // 32 MB
__device__ int    g_idx[2 * OUT_DIM];                          // 512 KB

__device__ __forceinline__ uint4 shfl4(uint4 v, int src) {
    uint4 r;
    r.x = __shfl_sync(0xffffffffu, v.x, src);
    r.y = __shfl_sync(0xffffffffu, v.y, src);
    r.z = __shfl_sync(0xffffffffu, v.z, src);
    r.w = __shfl_sync(0xffffffffu, v.w, src);
    return r;
}

// ---------------- fused prep: TMA transpose + coef + idx ----------------
__global__ __launch_bounds__(256) void prep_kernel(const float* __restrict__ x,
                                                   const float* __restrict__ wts,
                                                   const void*  __restrict__ idxraw) {
    // 64 rows of 132 floats (528B stride: 16B-aligned for TMA, odd*4 mod 32
    // banks for conflict-free warp-row reads)
    __shared__ __align__(16) float traw[64 * 132];        // 33792 B
    __shared__ __align__(8)  unsigned long long mbar;
    int bx  = blockIdx.x;
    int tid = threadIdx.x;

    if (bx < NB_T) {
        int it = bx & 511, bt = bx >> 9;
        int i0 = it * 128, b0 = bt * 64;

        unsigned mb = (unsigned)__cvta_generic_to_shared(&mbar);
        unsigned sb = (unsigned)__cvta_generic_to_shared(traw);

        if (tid == 0)
            asm volatile("mbarrier.init.shared.b64 [%0], %1;"
                         :: "r"(mb), "r"(1) : "memory");
        __syncthreads();

        if (tid == 0) {
            asm volatile("mbarrier.arrive.expect_tx.shared.b64 _, [%0], %1;"
                         :: "r"(mb), "r"(64 * 512) : "memory");
            const float* src = x + (size_t)b0 * IN_DIM + i0;
            #pragma unroll 1
            for (int r = 0; r < 64; r++) {
                asm volatile(
                    "cp.async.bulk.shared::cluster.global.mbarrier::complete_tx::bytes "
                    "[%0], [%1], %2, [%3];"
                    :: "r"(sb + r * 528), "l"(src + (size_t)r * IN_DIM),
                       "r"(512), "r"(mb) : "memory");
            }
        }
        // wait for all 32KB to land
        {
            unsigned done = 0;
            while (!done) {
                asm volatile(
                    "{\n\t.reg .pred p;\n\t"
                    "mbarrier.try_wait.parity.shared.b64 p, [%1], %2;\n\t"
                    "selp.b32 %0, 1, 0, p;\n\t}"
                    : "=r"(done) : "r"(mb), "r"(0) : "memory");
            }
        }

        // pack: warp reads 32-consecutive-input row segments (conflict-free),
        // each thread ends holding xt[i][32 batches] as 4x uint4 chunks
        int w = tid >> 5, l = tid & 31;
        int ig = (w & 3) * 32 + l;        // input column 0..127
        int bh = w >> 2;                  // batch half 0..1
        float v[32];
        #pragma unroll
        for (int r = 0; r < 32; r++)
            v[r] = traw[(bh * 32 + r) * 132 + ig];

        uint4 u[4];
        #pragma unroll
        for (int c = 0; c < 4; c++) {
            __half2 h0 = __floats2half2_rn(v[8*c + 0], v[8*c + 1]);
            __half2 h1 = __floats2half2_rn(v[8*c + 2], v[8*c + 3]);
            __half2 h2 = __floats2half2_rn(v[8*c + 4], v[8*c + 5]);
            __half2 h3 = __floats2half2_rn(v[8*c + 6], v[8*c + 7]);
            u[c] = make_uint4(*(unsigned*)&h0, *(unsigned*)&h1,
                              *(unsigned*)&h2, *(unsigned*)&h3);
        }

        // shfl regroup: round q stores rows 8q..8q+7 of this warp's i-group,
        // 4 lanes x 16B per row -> 8 lines per STG.128 inst
        int sel = l & 3;
        #pragma unroll
        for (int q = 0; q < 4; q++) {
            int srcl = 8 * q + (l >> 2);
            uint4 t0 = shfl4(u[0], srcl);
            uint4 t1 = shfl4(u[1], srcl);
            uint4 t2 = shfl4(u[2], srcl);
            uint4 t3 = shfl4(u[3], srcl);
            uint4 g = (sel == 0) ? t0 : (sel == 1) ? t1 : (sel == 2) ? t2 : t3;
            int row = i0 + (w & 3) * 32 + 8 * q + (l >> 2);
            char* dst = (char*)g_xth + (size_t)row * 512 + b0 * 2 + bh * 64 + sel * 16;
            *(uint4*)dst = g;
        }
    } else if (bx < NB_T + NB_C) {
        // softmax -> bilinear coefficients
        int o = (bx - NB_T) * 256 + tid;
        float p[16];
        const float4* w4 = (const float4*)(wts + (size_t)o * 16);
        float4 q0 = w4[0], q1 = w4[1], q2 = w4[2], q3 = w4[3];
        p[0]=q0.x; p[1]=q0.y; p[2]=q0.z; p[3]=q0.w;
        p[4]=q1.x; p[5]=q1.y; p[6]=q1.z; p[7]=q1.w;
        p[8]=q2.x; p[9]=q2.y; p[10]=q2.z; p[11]=q2.w;
        p[12]=q3.x; p[13]=q3.y; p[14]=q3.z; p[15]=q3.w;
        float m = p[0];
        #pragma unroll
        for (int i = 1; i < 16; i++) m = fmaxf(m, p[i]);
        float s = 0.f;
        #pragma unroll
        for (int i = 0; i < 16; i++) { p[i] = __expf(p[i] - m); s += p[i]; }
        float inv = 1.0f / s;
        #pragma unroll
        for (int i = 0; i < 16; i++) p[i] *= inv;
        float4 c;
        c.x = p[8]+p[9]+p[10]+p[11]+p[12]+p[13]+p[14]+p[15];
        c.y = p[2]+p[3]+p[6]+p[7]-p[8]-p[9]-p[12]-p[13];
        c.z = p[4]+p[5]+p[6]+p[7]-p[8]-p[9]-p[10]-p[11];
        c.w = p[1]-p[2]-p[4]-2.f*p[6]-p[7]+p[8]+2.f*p[9]+p[11]+p[13]-p[14];
        g_coef[o] = c;
    } else {
        __shared__ int s64;
        if (tid == 0) {
            const long long* p = (const long long*)idxraw;
            int is64 = 1;
            #pragma unroll 1
            for (int j = 0; j < 64; j++) {
                long long vv = p[j];
                if (vv < 0 || vv >= IN_DIM) { is64 = 0; break; }
            }
            s64 = is64;
        }
        __syncthreads();
        int i = (bx - NB_T - NB_C) * 256 + tid;
        g_idx[i] = s64 ? (int)((const long long*)idxraw)[i]
                       : ((const int*)idxraw)[i];
    }
}

// ---------------- main: R4-exact (best measured: 20.5us) ----------------
#define SWZ(b) ((20 * (((b) >> 2) & 7) + (((b) >> 5) & 7)) & 31)

__global__ __launch_bounds__(256, 4) void logic_main_kernel(float* __restrict__ out) {
    __shared__ float s[BATCH * 32];           // 32 KB
    int tid = threadIdx.x;
    int w = tid >> 5;
    int l = tid & 31;
    int ob = blockIdx.x * 32;
    int n0 = w * 4;

    int ia[4], ib[4];
    #pragma unroll
    for (int c = 0; c < 4; c++) {
        int o = ob + n0 + c;
        ia[c] = g_idx[o];
        ib[c] = g_idx[OUT_DIM + o];
    }
    uint4 va[4], vb[4];
    #pragma unroll
    for (int c = 0; c < 4; c++) {
        va[c] = ((const uint4*)(g_xth + (size_t)ia[c] * BATCH))[l];
        vb[c] = ((const uint4*)(g_xth + (size_t)ib[c] * BATCH))[l];
    }

    #pragma unroll
    for (int c = 0; c < 4; c++) {
        float4 cf = g_coef[ob + n0 + c];
        union { uint4 u; __half2 h[4]; } A, Bv;
        A.u = va[c]; Bv.u = vb[c];
        int n = n0 + c;
        int bbase = 8 * l;
        #pragma unroll
        for (int k2 = 0; k2 < 4; k2++) {
            float2 a = __half22float2(A.h[k2]);
            float2 b = __half22float2(Bv.h[k2]);
            float v0 = fmaf(fmaf(cf.w, b.x, cf.y), a.x, fmaf(cf.z, b.x, cf.x));
            float v1 = fmaf(fmaf(cf.w, b.y, cf.y), a.y, fmaf(cf.z, b.y, cf.x));
            int b0i = bbase + 2 * k2;
            int b1i = b0i + 1;
            s[b0i * 32 + ((n + SWZ(b0i)) & 31)] = v0;
            s[b1i * 32 + ((n + SWZ(b1i)) & 31)] = v1;
        }
    }
    __syncthreads();

    #pragma unroll
    for (int j = 0; j < 32; j++) {
        int b = w * 32 + j;
        __stcs(out + (size_t)b * OUT_DIM + ob + l,
               s[b * 32 + ((l + SWZ(b)) & 31)]);
    }
}

// ---------------- launch ------------------------------------------------
extern "C" void kernel_launch(void* const* d_in, const int* in_sizes, int n_in,
                              void* d_out, int out_size) {
    const float* x   = (const float*)d_in[0];
    const float* wts = (const float*)d_in[1];
    const void*  idx = d_in[2];
    float* out = (float*)d_out;

    prep_kernel<<<NB_T + NB_C + NB_I, 256>>>(x, wts, idx);
    logic_main_kernel<<<OUT_DIM / 32, 256>>>(out);
}

// round 14
// speedup vs baseline: 1.3551x; 1.0847x over previous
#include <cuda_runtime.h>
#include <cuda_fp16.h>

#define BATCH   256
#define IN_DIM  65536
#define OUT_DIM 65536

#define NB_T 2048   // transpose tiles: (IN/128) x (B/64)
#define NB_C 256
#define NB_I 512

// ---------------- device scratch ----------------------------------------
__device__ float4 g_coef[OUT_DIM];                             // 1 MB
__device__ __align__(16) __half g_xth[(size_t)IN_DIM * BATCH]; // 32 MB
__device__ int    g_idx[2 * OUT_DIM];                          // 512 KB

// ---------------- fused prep: transpose + coef + idx (R6, proven) -------
__global__ __launch_bounds__(256) void prep_kernel(const float* __restrict__ x,
                                                   const float* __restrict__ wts,
                                                   const void*  __restrict__ idxraw) {
    __shared__ float t[4][64][33];
    int bx  = blockIdx.x;
    int tid = threadIdx.x;

    if (bx < NB_T) {
        int it = bx & 511, bt = bx >> 9;
        int i0 = it * 128, b0 = bt * 64;
        int tx = tid & 7, ty = tid >> 3;

        const float4* r0 = (const float4*)(x + (size_t)(b0 + ty)      * IN_DIM + i0);
        const float4* r1 = (const float4*)(x + (size_t)(b0 + 32 + ty) * IN_DIM + i0);
        float4 v0[4], v1[4];
        #pragma unroll
        for (int h = 0; h < 4; h++) {
            v0[h] = __ldcs(r0 + tx + 8 * h);
            v1[h] = __ldcs(r1 + tx + 8 * h);
        }
        #pragma unroll
        for (int h = 0; h < 4; h++) {
            t[h][ty   ][tx*4+0]=v0[h].x; t[h][ty   ][tx*4+1]=v0[h].y;
            t[h][ty   ][tx*4+2]=v0[h].z; t[h][ty   ][tx*4+3]=v0[h].w;
            t[h][ty+32][tx*4+0]=v1[h].x; t[h][ty+32][tx*4+1]=v1[h].y;
            t[h][ty+32][tx*4+2]=v1[h].z; t[h][ty+32][tx*4+3]=v1[h].w;
        }
        __syncthreads();
        #pragma unroll
        for (int h = 0; h < 4; h++) {
            union { uint4 u; __half2 hh[4]; } pk;
            #pragma unroll
            for (int k = 0; k < 4; k++)
                pk.hh[k] = __floats2half2_rn(t[h][8*tx + 2*k][ty], t[h][8*tx + 2*k + 1][ty]);
            *(uint4*)(g_xth + (size_t)(i0 + 32*h + ty) * BATCH + b0 + 8*tx) = pk.u;
        }
    } else if (bx < NB_T + NB_C) {
        int o = (bx - NB_T) * 256 + tid;
        float p[16];
        const float4* w4 = (const float4*)(wts + (size_t)o * 16);
        float4 q0 = w4[0], q1 = w4[1], q2 = w4[2], q3 = w4[3];
        p[0]=q0.x; p[1]=q0.y; p[2]=q0.z; p[3]=q0.w;
        p[4]=q1.x; p[5]=q1.y; p[6]=q1.z; p[7]=q1.w;
        p[8]=q2.x; p[9]=q2.y; p[10]=q2.z; p[11]=q2.w;
        p[12]=q3.x; p[13]=q3.y; p[14]=q3.z; p[15]=q3.w;
        float m = p[0];
        #pragma unroll
        for (int i = 1; i < 16; i++) m = fmaxf(m, p[i]);
        float s = 0.f;
        #pragma unroll
        for (int i = 0; i < 16; i++) { p[i] = __expf(p[i] - m); s += p[i]; }
        float inv = 1.0f / s;
        #pragma unroll
        for (int i = 0; i < 16; i++) p[i] *= inv;
        float4 c;
        c.x = p[8]+p[9]+p[10]+p[11]+p[12]+p[13]+p[14]+p[15];
        c.y = p[2]+p[3]+p[6]+p[7]-p[8]-p[9]-p[12]-p[13];
        c.z = p[4]+p[5]+p[6]+p[7]-p[8]-p[9]-p[10]-p[11];
        c.w = p[1]-p[2]-p[4]-2.f*p[6]-p[7]+p[8]+2.f*p[9]+p[11]+p[13]-p[14];
        g_coef[o] = c;
    } else {
        __shared__ int s64;
        if (tid == 0) {
            const long long* p = (const long long*)idxraw;
            int is64 = 1;
            #pragma unroll 1
            for (int j = 0; j < 64; j++) {
                long long v = p[j];
                if (v < 0 || v >= IN_DIM) { is64 = 0; break; }
            }
            s64 = is64;
        }
        __syncthreads();
        int i = (bx - NB_T - NB_C) * 256 + tid;
        g_idx[i] = s64 ? (int)((const long long*)idxraw)[i]
                       : ((const int*)idxraw)[i];
    }
}

// ---------------- main: 128-bit staged, 8 warps x 4 neurons -------------
// Lane l holds, per batch row r=8l+k, a float4 of its warp's 4 CONSECUTIVE
// neurons -> stage + read + write are all 128-bit:
//   STS.128  s[r*32 + 4*((w+l)&7)]          (bank-quad w+l: conflict-free)
//   LDS.128  row r, quad (q + (r>>3))&7     (8 rotated quads: conflict-free)
//   STG.128  out[r][ob+4q]                  (contiguous 128B per 8 lanes)
// Per-warp LSU instructions: 8 LDG + 8 STS + 8 LDS + 8 STG = 32 (vs 104).
__global__ __launch_bounds__(256, 3) void logic_main_kernel(float* __restrict__ out) {
    __shared__ __align__(16) float s[BATCH * 32];   // 32 KB
    int tid = threadIdx.x;
    int w = tid >> 5;
    int l = tid & 31;
    int ob = blockIdx.x * 32;
    int n0 = w * 4;

    int ia[4], ib[4];
    #pragma unroll
    for (int c = 0; c < 4; c++) {
        int o = ob + n0 + c;
        ia[c] = g_idx[o];
        ib[c] = g_idx[OUT_DIM + o];
    }
    uint4 va[4], vb[4];
    #pragma unroll
    for (int c = 0; c < 4; c++) {
        va[c] = ((const uint4*)(g_xth + (size_t)ia[c] * BATCH))[l];
        vb[c] = ((const uint4*)(g_xth + (size_t)ib[c] * BATCH))[l];
    }
    float4 cf[4];
    #pragma unroll
    for (int c = 0; c < 4; c++) cf[c] = g_coef[ob + n0 + c];

    // k-outer: one float4 (4 neurons at batch row 8l+k) live at a time
    int colq4 = 4 * ((w + l) & 7);
    #pragma unroll
    for (int k = 0; k < 8; k++) {
        float v[4];
        #pragma unroll
        for (int c = 0; c < 4; c++) {
            const __half2* Ah = (const __half2*)&va[c];
            const __half2* Bh = (const __half2*)&vb[c];
            float2 a2 = __half22float2(Ah[k >> 1]);
            float2 b2 = __half22float2(Bh[k >> 1]);
            float a = (k & 1) ? a2.y : a2.x;
            float b = (k & 1) ? b2.y : b2.x;
            v[c] = fmaf(fmaf(cf[c].w, b, cf[c].y), a, fmaf(cf[c].z, b, cf[c].x));
        }
        *(float4*)&s[(8 * l + k) * 32 + colq4] = make_float4(v[0], v[1], v[2], v[3]);
    }
    __syncthreads();

    // warp w reads+writes rows 32w..32w+31, 4 rows per instruction pair
    int q = l & 7;
    int rsub = l >> 3;
    #pragma unroll
    for (int g = 0; g < 8; g++) {
        int row = w * 32 + 4 * g + rsub;
        int c4 = (q + (row >> 3)) & 7;
        float4 val = *(const float4*)&s[row * 32 + 4 * c4];
        __stcs((float4*)(out + (size_t)row * OUT_DIM + ob + 4 * q), val);
    }
}

// ---------------- launch ------------------------------------------------
extern "C" void kernel_launch(void* const* d_in, const int* in_sizes, int n_in,
                              void* d_out, int out_size) {
    const float* x   = (const float*)d_in[0];
    const float* wts = (const float*)d_in[1];
    const void*  idx = d_in[2];
    float* out = (float*)d_out;

    prep_kernel<<<NB_T + NB_C + NB_I, 256>>>(x, wts, idx);
    logic_main_kernel<<<OUT_DIM / 32, 256>>>(out);
}